// round 1
// baseline (speedup 1.0000x reference)
#include <cuda_runtime.h>

// ---------------- problem constants ----------------
#define B_   32
#define T_   128
#define D_   512
#define H_   8
#define HD_  64
#define FF_  2048
#define E_   8
#define NL_  3
#define NF_  16
#define FEAT_ 200
#define NTOK  4096          // B*T
#define NSLOT 8192          // NTOK*2 (top-2 slots)
#define SCALE_ 10.0f
#define EPS_   1e-5f

// ---------------- scratch (device globals; no allocation allowed) ----------------
__device__ float g_x  [NTOK * D_];
__device__ float g_pb [B_ * T_ * T_];
__device__ float g_K  [NTOK * D_];
__device__ float g_V  [NTOK * D_];
__device__ float g_kv [B_ * D_];
__device__ float g_wv [NTOK * D_];
__device__ float g_o  [NTOK * D_];
__device__ float g_h  [(NSLOT + 128) * FF_];
__device__ float g_eo [(NSLOT + 128) * D_];
__device__ int   g_te [NSLOT];
__device__ float g_tw [NSLOT];
__device__ int   g_cnt[E_];
__device__ int   g_off[E_ + 1];
__device__ int   g_cur[E_];
__device__ int   g_tok[NSLOT + 128];
__device__ int   g_pos[NSLOT];

// ---------------- generic 128x128x8 fp32 GEMM core ----------------
#define BM 128
#define BN 128
#define BK 8

__device__ __forceinline__ float4 ld4(const float* p) {
    return *reinterpret_cast<const float4*>(p);
}

// C[M,N] = op( gather(A)[M,K] @ B[K,N] + bias + addvec )
// A row-major with lda; B row-major with ldb; 256 threads/block; 8x8 per thread.
template <bool GATHER, bool RELU, bool ADDVEC>
__device__ __forceinline__ void gemm_core(
    const float* __restrict__ A, int lda, const int* __restrict__ rowmap,
    const float* __restrict__ B, int ldb,
    const float* __restrict__ bias, const float* __restrict__ addvec,
    float* __restrict__ C, int ldc,
    int M, int N, int K, int mtile, int ntile)
{
    __shared__ float As[BK][BM + 4];
    __shared__ float Bs[BK][BN];

    const int tid = threadIdx.x;
    const int tx = tid & 15;
    const int ty = tid >> 4;

    // A tile load mapping: each thread loads one float4 (row arow, cols acol..acol+3)
    const int arow = tid >> 1;
    const int acol = (tid & 1) * 4;
    int gm_a = mtile * BM + arow;
    if (gm_a > M - 1) gm_a = M - 1;
    const int ra = GATHER ? rowmap[gm_a] : gm_a;
    const float* Ap = A + (size_t)ra * lda + acol;

    // B tile load mapping: each thread loads one float4
    const int brow = tid >> 5;
    const int bcol = (tid & 31) * 4;
    const float* Bp = B + (size_t)brow * ldb + ntile * BN + bcol;

    float acc[8][8];
#pragma unroll
    for (int i = 0; i < 8; i++)
#pragma unroll
        for (int j = 0; j < 8; j++) acc[i][j] = 0.f;

    const int nk = K / BK;
    const int bstep = BK * ldb;

    float4 av = ld4(Ap);
    float4 bv = ld4(Bp);

    for (int kt = 0; kt < nk; kt++) {
        As[acol + 0][arow] = av.x;
        As[acol + 1][arow] = av.y;
        As[acol + 2][arow] = av.z;
        As[acol + 3][arow] = av.w;
        *reinterpret_cast<float4*>(&Bs[brow][bcol]) = bv;
        __syncthreads();

        if (kt + 1 < nk) {
            Ap += BK;
            Bp += bstep;
            av = ld4(Ap);
            bv = ld4(Bp);
        }

#pragma unroll
        for (int kk = 0; kk < BK; kk++) {
            float a[8], b[8];
#pragma unroll
            for (int i = 0; i < 8; i++) a[i] = As[kk][ty * 8 + i];
#pragma unroll
            for (int j = 0; j < 8; j++) b[j] = Bs[kk][tx * 8 + j];
#pragma unroll
            for (int i = 0; i < 8; i++)
#pragma unroll
                for (int j = 0; j < 8; j++) acc[i][j] += a[i] * b[j];
        }
        __syncthreads();
    }

#pragma unroll
    for (int i = 0; i < 8; i++) {
        const int gm = mtile * BM + ty * 8 + i;
        if (gm < M) {
            float* Crow = C + (size_t)gm * ldc + ntile * BN + tx * 8;
#pragma unroll
            for (int j = 0; j < 8; j++) {
                const int gn = ntile * BN + tx * 8 + j;
                float v = acc[i][j];
                if (bias) v += bias[gn];
                if (ADDVEC) v += addvec[gn];
                if (RELU) v = fmaxf(v, 0.f);
                Crow[j] = v;
            }
        }
    }
}

// ---------------- GEMM kernel wrappers ----------------
__global__ __launch_bounds__(256) void k_embed(
    const int* __restrict__ src, const float* __restrict__ tab,
    const float* __restrict__ W, const float* __restrict__ bias,
    float* __restrict__ C)
{
    gemm_core<true, false, false>(tab, FEAT_, src, W, D_, bias, nullptr,
                                  C, D_, NTOK, D_, FEAT_, blockIdx.y, blockIdx.x);
}

__global__ __launch_bounds__(256) void k_gemm(
    const float* __restrict__ A, const float* __restrict__ B,
    const float* __restrict__ bias, float* __restrict__ C,
    int M, int N, int K)
{
    gemm_core<false, false, false>(A, K, nullptr, B, N, bias, nullptr,
                                   C, N, M, N, K, blockIdx.y, blockIdx.x);
}

__global__ __launch_bounds__(256) void k_pbv(
    const float* __restrict__ pb, const float* __restrict__ V,
    const float* __restrict__ kv, float* __restrict__ wv)
{
    const int b = blockIdx.z;
    gemm_core<false, false, true>(pb + (size_t)b * T_ * T_, T_, nullptr,
                                  V + (size_t)b * T_ * D_, D_,
                                  nullptr, kv + (size_t)b * D_,
                                  wv + (size_t)b * T_ * D_, D_,
                                  T_, D_, T_, 0, blockIdx.x);
}

__global__ __launch_bounds__(256) void k_moe1(
    const float* __restrict__ x, const float* __restrict__ W1,
    const float* __restrict__ b1)
{
    const int e = blockIdx.z;
    const int Me = g_cnt[e];
    if ((int)(blockIdx.y * BM) >= Me) return;
    gemm_core<true, true, false>(x, D_, g_tok + g_off[e],
                                 W1 + (size_t)e * D_ * FF_, FF_,
                                 b1 + (size_t)e * FF_, nullptr,
                                 g_h + (size_t)g_off[e] * FF_, FF_,
                                 Me, FF_, D_, blockIdx.y, blockIdx.x);
}

__global__ __launch_bounds__(256) void k_moe2(
    const float* __restrict__ W2, const float* __restrict__ b2)
{
    const int e = blockIdx.z;
    const int Me = g_cnt[e];
    if ((int)(blockIdx.y * BM) >= Me) return;
    gemm_core<false, false, false>(g_h + (size_t)g_off[e] * FF_, FF_, nullptr,
                                   W2 + (size_t)e * FF_ * D_, D_,
                                   b2 + (size_t)e * D_, nullptr,
                                   g_eo + (size_t)g_off[e] * D_, D_,
                                   Me, D_, FF_, blockIdx.y, blockIdx.x);
}

// ---------------- Fourier positional bias ----------------
__global__ void k_pb(const float* __restrict__ frac,
                     const float* __restrict__ pbW,
                     const float* __restrict__ pbb,
                     const float* __restrict__ pba,
                     float* __restrict__ pb)
{
    __shared__ float w[NF_], ph[NF_], am[NF_];
    if (threadIdx.x < NF_) {
        w[threadIdx.x]  = pbW[threadIdx.x];
        ph[threadIdx.x] = pbb[threadIdx.x];
        am[threadIdx.x] = pba[threadIdx.x];
    }
    __syncthreads();
    const int idx = blockIdx.x * 256 + threadIdx.x;   // < 32*128*128
    const int j = idx & 127;
    const int i = (idx >> 7) & 127;
    const int b = idx >> 14;
    const float d = (frac[b * T_ + j] - frac[b * T_ + i]) * SCALE_;
    float s = 0.f;
#pragma unroll
    for (int f = 0; f < NF_; f++) s += am[f] * cosf(d * w[f] + ph[f]);
    pb[idx] = s;
}

// ---------------- kv reduction: kv[b,d] = sum_t K[b,t,d]*V[b,t,d] ----------------
__global__ void k_kv(const float* __restrict__ K, const float* __restrict__ V,
                     float* __restrict__ kv)
{
    const int b = blockIdx.x;
    const int d = threadIdx.x;     // 512 threads
    const float* Kb = K + (size_t)b * T_ * D_ + d;
    const float* Vb = V + (size_t)b * T_ * D_ + d;
    float s = 0.f;
#pragma unroll 8
    for (int t = 0; t < T_; t++) s += Kb[t * D_] * Vb[t * D_];
    kv[b * D_ + d] = s;
}

// ---------------- block reduction helper (256 threads) ----------------
__device__ __forceinline__ float blk_sum_256(float v, float* red) {
    const unsigned m = 0xffffffffu;
#pragma unroll
    for (int o = 16; o > 0; o >>= 1) v += __shfl_down_sync(m, v, o);
    if ((threadIdx.x & 31) == 0) red[threadIdx.x >> 5] = v;
    __syncthreads();
    if (threadIdx.x < 32) {
        float r = (threadIdx.x < 8) ? red[threadIdx.x] : 0.f;
#pragma unroll
        for (int o = 4; o > 0; o >>= 1) r += __shfl_down_sync(m, r, o);
        if (threadIdx.x == 0) red[0] = r;
    }
    __syncthreads();
    const float r = red[0];
    __syncthreads();
    return r;
}

// ---------------- LN1: out = LN(x + y) ----------------
__global__ void k_ln(const float* __restrict__ x, const float* __restrict__ y,
                     const float* __restrict__ g, const float* __restrict__ b,
                     float* __restrict__ out)
{
    __shared__ float red[8];
    const int t = blockIdx.x;
    const int tid = threadIdx.x;      // 256
    const float* xr = x + (size_t)t * D_;
    const float* yr = y + (size_t)t * D_;
    const float v0 = xr[tid]       + yr[tid];
    const float v1 = xr[tid + 256] + yr[tid + 256];
    const float mean = blk_sum_256(v0 + v1, red) * (1.f / D_);
    const float d0 = v0 - mean, d1 = v1 - mean;
    const float var = blk_sum_256(d0 * d0 + d1 * d1, red) * (1.f / D_);
    const float inv = rsqrtf(var + EPS_);
    out[(size_t)t * D_ + tid]       = d0 * inv * g[tid]       + b[tid];
    out[(size_t)t * D_ + tid + 256] = d1 * inv * g[tid + 256] + b[tid + 256];
}

// ---------------- gating: softmax + top-2 ----------------
__global__ void k_gate(const float* __restrict__ x, const float* __restrict__ gW,
                       const float* __restrict__ gb)
{
    __shared__ float xs[D_];
    __shared__ float lg[E_];
    const int t = blockIdx.x;
    const int tid = threadIdx.x;     // 256
    xs[tid]       = x[(size_t)t * D_ + tid];
    xs[tid + 256] = x[(size_t)t * D_ + tid + 256];
    __syncthreads();

    const int e = tid >> 5;          // one warp per expert
    const int lane = tid & 31;
    float s = 0.f;
    for (int k = lane; k < D_; k += 32) s += xs[k] * gW[k * E_ + e];
    const unsigned m = 0xffffffffu;
#pragma unroll
    for (int o = 16; o > 0; o >>= 1) s += __shfl_down_sync(m, s, o);
    if (lane == 0) lg[e] = s + gb[e];
    __syncthreads();

    if (tid == 0) {
        float mx = lg[0];
#pragma unroll
        for (int k = 1; k < E_; k++) mx = fmaxf(mx, lg[k]);
        float ex[E_]; float sum = 0.f;
#pragma unroll
        for (int k = 0; k < E_; k++) { ex[k] = expf(lg[k] - mx); sum += ex[k]; }
        const float inv = 1.f / sum;
        int e0 = 0; float p0 = ex[0];
#pragma unroll
        for (int k = 1; k < E_; k++) if (ex[k] > p0) { p0 = ex[k]; e0 = k; }
        int e1 = -1; float p1 = -1.f;
#pragma unroll
        for (int k = 0; k < E_; k++)
            if (k != e0 && ex[k] > p1) { p1 = ex[k]; e1 = k; }
        g_te[2 * t]     = e0; g_tw[2 * t]     = p0 * inv;
        g_te[2 * t + 1] = e1; g_tw[2 * t + 1] = p1 * inv;
        atomicAdd(&g_cnt[e0], 1);
        atomicAdd(&g_cnt[e1], 1);
    }
}

__global__ void k_zero8() {
    if (threadIdx.x < E_) g_cnt[threadIdx.x] = 0;
}

__global__ void k_scan() {
    if (threadIdx.x == 0) {
        int a = 0;
        for (int e = 0; e < E_; e++) { g_off[e] = a; g_cur[e] = a; a += g_cnt[e]; }
        g_off[E_] = a;
    }
}

__global__ void k_scatter() {
    const int t = blockIdx.x * 256 + threadIdx.x;
    if (t >= NTOK) return;
#pragma unroll
    for (int k = 0; k < 2; k++) {
        const int e = g_te[2 * t + k];
        const int p = atomicAdd(&g_cur[e], 1);
        g_tok[p] = t;
        g_pos[2 * t + k] = p;
    }
}

// ---------------- LN2: out = LN(x + w0*eo[p0] + w1*eo[p1]) ----------------
__global__ void k_ln2(const float* __restrict__ x,
                      const float* __restrict__ g, const float* __restrict__ b,
                      float* __restrict__ out)
{
    __shared__ float red[8];
    const int t = blockIdx.x;
    const int tid = threadIdx.x;     // 256
    const int p0 = g_pos[2 * t], p1 = g_pos[2 * t + 1];
    const float w0 = g_tw[2 * t], w1 = g_tw[2 * t + 1];
    const float* e0 = g_eo + (size_t)p0 * D_;
    const float* e1 = g_eo + (size_t)p1 * D_;
    const float* xr = x + (size_t)t * D_;
    const float v0 = xr[tid]       + w0 * e0[tid]       + w1 * e1[tid];
    const float v1 = xr[tid + 256] + w0 * e0[tid + 256] + w1 * e1[tid + 256];
    const float mean = blk_sum_256(v0 + v1, red) * (1.f / D_);
    const float d0 = v0 - mean, d1 = v1 - mean;
    const float var = blk_sum_256(d0 * d0 + d1 * d1, red) * (1.f / D_);
    const float inv = rsqrtf(var + EPS_);
    out[(size_t)t * D_ + tid]       = d0 * inv * g[tid]       + b[tid];
    out[(size_t)t * D_ + tid + 256] = d1 * inv * g[tid + 256] + b[tid + 256];
}

// ---------------- host launcher ----------------
extern "C" void kernel_launch(void* const* d_in, const int* in_sizes, int n_in,
                              void* d_out, int out_size)
{
    const int*   src  = (const int*)  d_in[0];
    const float* frac = (const float*)d_in[1];
    const float* tab  = (const float*)d_in[2];
    const float* Wm2v = (const float*)d_in[3];
    const float* bm2v = (const float*)d_in[4];
    const float* pbW  = (const float*)d_in[5];
    const float* pbb  = (const float*)d_in[6];
    const float* pba  = (const float*)d_in[7];
    const float* Wk   = (const float*)d_in[8];
    const float* bk   = (const float*)d_in[9];
    const float* Wv   = (const float*)d_in[10];
    const float* bv   = (const float*)d_in[11];
    const float* Wo   = (const float*)d_in[12];
    const float* bo   = (const float*)d_in[13];
    const float* ln1g = (const float*)d_in[14];
    const float* ln1b = (const float*)d_in[15];
    const float* ln2g = (const float*)d_in[16];
    const float* ln2b = (const float*)d_in[17];
    const float* gW   = (const float*)d_in[18];
    const float* gb   = (const float*)d_in[19];
    const float* eW1  = (const float*)d_in[20];
    const float* eb1  = (const float*)d_in[21];
    const float* eW2  = (const float*)d_in[22];
    const float* eb2  = (const float*)d_in[23];

    float *x, *pb, *Kb, *Vb, *kvb, *wv, *o;
    cudaGetSymbolAddress((void**)&x,   g_x);
    cudaGetSymbolAddress((void**)&pb,  g_pb);
    cudaGetSymbolAddress((void**)&Kb,  g_K);
    cudaGetSymbolAddress((void**)&Vb,  g_V);
    cudaGetSymbolAddress((void**)&kvb, g_kv);
    cudaGetSymbolAddress((void**)&wv,  g_wv);
    cudaGetSymbolAddress((void**)&o,   g_o);

    const dim3 g44(4, 32);        // N=512 tiles x M=4096 tiles

    // x = embed_table[src] @ W_m2v + b
    k_embed<<<g44, 256>>>(src, tab, Wm2v, bm2v, x);
    // positional bias
    k_pb<<<(B_ * T_ * T_) / 256, 256>>>(frac, pbW, pbb, pba, pb);

    for (int i = 0; i < NL_; i++) {
        const size_t wOff = (size_t)i * D_ * D_;
        k_gemm<<<g44, 256>>>(x,  Wk + wOff, bk + i * D_, Kb, NTOK, D_, D_);
        k_gemm<<<g44, 256>>>(x,  Wv + wOff, bv + i * D_, Vb, NTOK, D_, D_);
        k_kv<<<B_, 512>>>(Kb, Vb, kvb);
        k_pbv<<<dim3(4, 1, B_), 256>>>(pb, Vb, kvb, wv);
        k_gemm<<<g44, 256>>>(wv, Wo + wOff, bo + i * D_, o, NTOK, D_, D_);
        k_ln<<<NTOK, 256>>>(x, o, ln1g + i * D_, ln1b + i * D_, x);

        k_zero8<<<1, 32>>>();
        k_gate<<<NTOK, 256>>>(x, gW + (size_t)i * D_ * E_, gb + i * E_);
        k_scan<<<1, 1>>>();
        k_scatter<<<NTOK / 256, 256>>>();

        k_moe1<<<dim3(FF_ / BN, 32, E_), 256>>>(
            x, eW1 + (size_t)i * E_ * D_ * FF_, eb1 + (size_t)i * E_ * FF_);
        k_moe2<<<dim3(D_ / BN, 32, E_), 256>>>(
            eW2 + (size_t)i * E_ * FF_ * D_, eb2 + (size_t)i * E_ * D_);

        float* dst = (i == NL_ - 1) ? (float*)d_out : x;
        k_ln2<<<NTOK, 256>>>(x, ln2g + i * D_, ln2b + i * D_, dst);
    }
}

// round 3
// speedup vs baseline: 1.2905x; 1.2905x over previous
#include <cuda_runtime.h>

// ---------------- problem constants ----------------
#define B_   32
#define T_   128
#define D_   512
#define H_   8
#define HD_  64
#define FF_  2048
#define E_   8
#define NL_  3
#define NF_  16
#define FEAT_ 200
#define NTOK  4096          // B*T
#define NSLOT 8192          // NTOK*2 (top-2 slots)
#define SCALE_ 10.0f
#define EPS_   1e-5f

// ---------------- scratch (device globals; no allocation allowed) ----------------
__device__ float g_x  [NTOK * D_];
__device__ float g_pb [B_ * T_ * T_];
__device__ float g_K  [NTOK * D_];
__device__ float g_V  [NTOK * D_];
__device__ float g_kv [B_ * D_];
__device__ float g_wv [NTOK * D_];
__device__ float g_o  [NTOK * D_];
__device__ float g_h  [(NSLOT + 128) * FF_];
__device__ float g_eo [(NSLOT + 128) * D_];
__device__ int   g_te [NSLOT];
__device__ float g_tw [NSLOT];
__device__ int   g_cnt[E_];
__device__ int   g_off[E_ + 1];
__device__ int   g_cur[E_];
__device__ int   g_tok[NSLOT + 128];
__device__ int   g_pos[NSLOT];

// ---------------- TF32 tensor-core GEMM core: 128x128x16, 3xTF32 ----------------
#define BM 128
#define BN 128
#define BK 16

__device__ __forceinline__ float4 ld4(const float* p) {
    return *reinterpret_cast<const float4*>(p);
}

// Split fp32 into hi+lo TF32 pair (error-compensated MMA).
__device__ __forceinline__ void split_tf32(float x, unsigned& hi, unsigned& lo) {
    unsigned h;
    asm("cvt.rna.tf32.f32 %0, %1;" : "=r"(h) : "f"(x));
    const float r = x - __uint_as_float(h);
    unsigned l;
    asm("cvt.rna.tf32.f32 %0, %1;" : "=r"(l) : "f"(r));
    hi = h; lo = l;
}

__device__ __forceinline__ void mma_tf32(float* c, const unsigned* a, const unsigned* b) {
    asm("mma.sync.aligned.m16n8k8.row.col.f32.tf32.tf32.f32 "
        "{%0,%1,%2,%3}, {%4,%5,%6,%7}, {%8,%9}, {%0,%1,%2,%3};"
        : "+f"(c[0]), "+f"(c[1]), "+f"(c[2]), "+f"(c[3])
        : "r"(a[0]), "r"(a[1]), "r"(a[2]), "r"(a[3]), "r"(b[0]), "r"(b[1]));
}

// C[M,N] = op( gather(A)[M,K] @ B[K,N] + bias + addvec )
// 256 threads = 8 warps (2x4), each warp 64x32 of m16n8k8 tiles.
template <bool GATHER, bool RELU, bool ADDVEC>
__device__ __forceinline__ void gemm_tc(
    const float* __restrict__ A, int lda, const int* __restrict__ rowmap,
    const float* __restrict__ B, int ldb,
    const float* __restrict__ bias, const float* __restrict__ addvec,
    float* __restrict__ C, int ldc,
    int M, int N, int K, int mtile, int ntile)
{
    __shared__ float As[2][BM][BK + 4];   // [stage][m][k]
    __shared__ float Bs[2][BK][BN + 8];   // [stage][k][n]

    const int tid  = threadIdx.x;
    const int lane = tid & 31;
    const int warp = tid >> 5;
    const int wm = (warp >> 2) * 64;      // 0 or 64
    const int wn = (warp & 3) * 32;       // 0,32,64,96
    const int gq  = lane >> 2;            // 0..7
    const int tig = lane & 3;             // 0..3

    // A tile loader: thread handles rows ar0, ar0+64, cols ac..ac+3 (of BK=16)
    const int ar0 = tid >> 2;             // 0..63
    const int ac  = (tid & 3) * 4;
    int gm0 = mtile * BM + ar0;       if (gm0 > M - 1) gm0 = M - 1;
    int gm1 = mtile * BM + ar0 + 64;  if (gm1 > M - 1) gm1 = M - 1;
    const int ra0 = GATHER ? rowmap[gm0] : gm0;
    const int ra1 = GATHER ? rowmap[gm1] : gm1;
    const float* Ap0 = A + (size_t)ra0 * lda + ac;
    const float* Ap1 = A + (size_t)ra1 * lda + ac;

    // B tile loader: thread handles k-rows br, br+8, cols bc..bc+3 (of BN=128)
    const int br = tid >> 5;              // 0..7
    const int bc = (tid & 31) * 4;
    const float* Bp = B + (size_t)br * ldb + ntile * BN + bc;

    float acc[4][4][4];
#pragma unroll
    for (int i = 0; i < 4; i++)
#pragma unroll
        for (int j = 0; j < 4; j++)
#pragma unroll
            for (int r = 0; r < 4; r++) acc[i][j][r] = 0.f;

    const int nk = (K + BK - 1) / BK;
    const float4 z4 = make_float4(0.f, 0.f, 0.f, 0.f);

    float4 a0v, a1v, b0v, b1v;
    // prefetch tile 0
    {
        a0v = (ac < K) ? ld4(Ap0) : z4;
        a1v = (ac < K) ? ld4(Ap1) : z4;
        b0v = (br < K) ? ld4(Bp) : z4;
        b1v = (br + 8 < K) ? ld4(Bp + (size_t)8 * ldb) : z4;
    }

    for (int kt = 0; kt < nk; kt++) {
        const int s = kt & 1;
        As[s][ar0][ac + 0] = a0v.x;
        As[s][ar0][ac + 1] = a0v.y;
        As[s][ar0][ac + 2] = a0v.z;
        As[s][ar0][ac + 3] = a0v.w;
        As[s][ar0 + 64][ac + 0] = a1v.x;
        As[s][ar0 + 64][ac + 1] = a1v.y;
        As[s][ar0 + 64][ac + 2] = a1v.z;
        As[s][ar0 + 64][ac + 3] = a1v.w;
        *reinterpret_cast<float4*>(&Bs[s][br][bc])     = b0v;
        *reinterpret_cast<float4*>(&Bs[s][br + 8][bc]) = b1v;
        __syncthreads();

        if (kt + 1 < nk) {
            const int kb = (kt + 1) * BK;
            a0v = (kb + ac < K) ? ld4(Ap0 + kb) : z4;
            a1v = (kb + ac < K) ? ld4(Ap1 + kb) : z4;
            b0v = (kb + br < K) ? ld4(Bp + (size_t)kb * ldb) : z4;
            b1v = (kb + br + 8 < K) ? ld4(Bp + (size_t)(kb + 8) * ldb) : z4;
        }

#pragma unroll
        for (int ks = 0; ks < 2; ks++) {
            const int kk = ks * 8;
            unsigned ahi[4][4], alo[4][4], bhi[4][2], blo[4][2];
#pragma unroll
            for (int mt = 0; mt < 4; mt++) {
                const int r0 = wm + mt * 16 + gq;
                split_tf32(As[s][r0]    [kk + tig],     ahi[mt][0], alo[mt][0]);
                split_tf32(As[s][r0 + 8][kk + tig],     ahi[mt][1], alo[mt][1]);
                split_tf32(As[s][r0]    [kk + tig + 4], ahi[mt][2], alo[mt][2]);
                split_tf32(As[s][r0 + 8][kk + tig + 4], ahi[mt][3], alo[mt][3]);
            }
#pragma unroll
            for (int nt = 0; nt < 4; nt++) {
                const int nn = wn + nt * 8 + gq;
                split_tf32(Bs[s][kk + tig]    [nn], bhi[nt][0], blo[nt][0]);
                split_tf32(Bs[s][kk + tig + 4][nn], bhi[nt][1], blo[nt][1]);
            }
            // correction terms first, big term last
#pragma unroll
            for (int mt = 0; mt < 4; mt++)
#pragma unroll
                for (int nt = 0; nt < 4; nt++) {
                    mma_tf32(acc[mt][nt], alo[mt], bhi[nt]);
                    mma_tf32(acc[mt][nt], ahi[mt], blo[nt]);
                    mma_tf32(acc[mt][nt], ahi[mt], bhi[nt]);
                }
        }
        __syncthreads();
    }

    // epilogue: c0:(g, 2t) c1:(g, 2t+1) c2:(g+8, 2t) c3:(g+8, 2t+1)
#pragma unroll
    for (int nt = 0; nt < 4; nt++) {
        const int gn = ntile * BN + wn + nt * 8 + 2 * tig;
        float bx = 0.f, by = 0.f;
        if (bias) { bx = bias[gn]; by = bias[gn + 1]; }
        if (ADDVEC) { bx += addvec[gn]; by += addvec[gn + 1]; }
#pragma unroll
        for (int mt = 0; mt < 4; mt++) {
            const int gm0w = mtile * BM + wm + mt * 16 + gq;
            float v0 = acc[mt][nt][0] + bx;
            float v1 = acc[mt][nt][1] + by;
            float v2 = acc[mt][nt][2] + bx;
            float v3 = acc[mt][nt][3] + by;
            if (RELU) {
                v0 = fmaxf(v0, 0.f); v1 = fmaxf(v1, 0.f);
                v2 = fmaxf(v2, 0.f); v3 = fmaxf(v3, 0.f);
            }
            if (gm0w < M)
                *reinterpret_cast<float2*>(C + (size_t)gm0w * ldc + gn) = make_float2(v0, v1);
            if (gm0w + 8 < M)
                *reinterpret_cast<float2*>(C + (size_t)(gm0w + 8) * ldc + gn) = make_float2(v2, v3);
        }
    }
}

// ---------------- GEMM kernel wrappers ----------------
__global__ __launch_bounds__(256) void k_embed(
    const int* __restrict__ src, const float* __restrict__ tab,
    const float* __restrict__ W, const float* __restrict__ bias,
    float* __restrict__ C)
{
    gemm_tc<true, false, false>(tab, FEAT_, src, W, D_, bias, nullptr,
                                C, D_, NTOK, D_, FEAT_, blockIdx.y, blockIdx.x);
}

__global__ __launch_bounds__(256) void k_gemm(
    const float* __restrict__ A, const float* __restrict__ B,
    const float* __restrict__ bias, float* __restrict__ C,
    int M, int N, int K)
{
    gemm_tc<false, false, false>(A, K, nullptr, B, N, bias, nullptr,
                                 C, N, M, N, K, blockIdx.y, blockIdx.x);
}

__global__ __launch_bounds__(256) void k_pbv(
    const float* __restrict__ pb, const float* __restrict__ V,
    const float* __restrict__ kv, float* __restrict__ wv)
{
    const int b = blockIdx.z;
    gemm_tc<false, false, true>(pb + (size_t)b * T_ * T_, T_, nullptr,
                                V + (size_t)b * T_ * D_, D_,
                                nullptr, kv + (size_t)b * D_,
                                wv + (size_t)b * T_ * D_, D_,
                                T_, D_, T_, 0, blockIdx.x);
}

__global__ __launch_bounds__(256) void k_moe1(
    const float* __restrict__ x, const float* __restrict__ W1,
    const float* __restrict__ b1)
{
    const int e = blockIdx.z;
    const int Me = g_cnt[e];
    if ((int)(blockIdx.y * BM) >= Me) return;
    gemm_tc<true, true, false>(x, D_, g_tok + g_off[e],
                               W1 + (size_t)e * D_ * FF_, FF_,
                               b1 + (size_t)e * FF_, nullptr,
                               g_h + (size_t)g_off[e] * FF_, FF_,
                               Me, FF_, D_, blockIdx.y, blockIdx.x);
}

__global__ __launch_bounds__(256) void k_moe2(
    const float* __restrict__ W2, const float* __restrict__ b2)
{
    const int e = blockIdx.z;
    const int Me = g_cnt[e];
    if ((int)(blockIdx.y * BM) >= Me) return;
    gemm_tc<false, false, false>(g_h + (size_t)g_off[e] * FF_, FF_, nullptr,
                                 W2 + (size_t)e * FF_ * D_, D_,
                                 b2 + (size_t)e * D_, nullptr,
                                 g_eo + (size_t)g_off[e] * D_, D_,
                                 Me, D_, FF_, blockIdx.y, blockIdx.x);
}

// ---------------- Fourier positional bias ----------------
__global__ void k_pb(const float* __restrict__ frac,
                     const float* __restrict__ pbW,
                     const float* __restrict__ pbb,
                     const float* __restrict__ pba,
                     float* __restrict__ pb)
{
    __shared__ float w[NF_], ph[NF_], am[NF_];
    if (threadIdx.x < NF_) {
        w[threadIdx.x]  = pbW[threadIdx.x];
        ph[threadIdx.x] = pbb[threadIdx.x];
        am[threadIdx.x] = pba[threadIdx.x];
    }
    __syncthreads();
    const int idx = blockIdx.x * 256 + threadIdx.x;   // < 32*128*128
    const int j = idx & 127;
    const int i = (idx >> 7) & 127;
    const int b = idx >> 14;
    const float d = (frac[b * T_ + j] - frac[b * T_ + i]) * SCALE_;
    float s = 0.f;
#pragma unroll
    for (int f = 0; f < NF_; f++) s += am[f] * cosf(d * w[f] + ph[f]);
    pb[idx] = s;
}

// ---------------- kv reduction: kv[b,d] = sum_t K[b,t,d]*V[b,t,d] ----------------
__global__ void k_kv(const float* __restrict__ K, const float* __restrict__ V,
                     float* __restrict__ kv)
{
    const int b = blockIdx.x;
    const int d = threadIdx.x;     // 512 threads
    const float* Kb = K + (size_t)b * T_ * D_ + d;
    const float* Vb = V + (size_t)b * T_ * D_ + d;
    float s = 0.f;
#pragma unroll 8
    for (int t = 0; t < T_; t++) s += Kb[t * D_] * Vb[t * D_];
    kv[b * D_ + d] = s;
}

// ---------------- block reduction helper (256 threads) ----------------
__device__ __forceinline__ float blk_sum_256(float v, float* red) {
    const unsigned m = 0xffffffffu;
#pragma unroll
    for (int o = 16; o > 0; o >>= 1) v += __shfl_down_sync(m, v, o);
    if ((threadIdx.x & 31) == 0) red[threadIdx.x >> 5] = v;
    __syncthreads();
    if (threadIdx.x < 32) {
        float r = (threadIdx.x < 8) ? red[threadIdx.x] : 0.f;
#pragma unroll
        for (int o = 4; o > 0; o >>= 1) r += __shfl_down_sync(m, r, o);
        if (threadIdx.x == 0) red[0] = r;
    }
    __syncthreads();
    const float r = red[0];
    __syncthreads();
    return r;
}

// ---------------- LN1: out = LN(x + y) ----------------
__global__ void k_ln(const float* __restrict__ x, const float* __restrict__ y,
                     const float* __restrict__ g, const float* __restrict__ b,
                     float* __restrict__ out)
{
    __shared__ float red[8];
    const int t = blockIdx.x;
    const int tid = threadIdx.x;      // 256
    const float* xr = x + (size_t)t * D_;
    const float* yr = y + (size_t)t * D_;
    const float v0 = xr[tid]       + yr[tid];
    const float v1 = xr[tid + 256] + yr[tid + 256];
    const float mean = blk_sum_256(v0 + v1, red) * (1.f / D_);
    const float d0 = v0 - mean, d1 = v1 - mean;
    const float var = blk_sum_256(d0 * d0 + d1 * d1, red) * (1.f / D_);
    const float inv = rsqrtf(var + EPS_);
    out[(size_t)t * D_ + tid]       = d0 * inv * g[tid]       + b[tid];
    out[(size_t)t * D_ + tid + 256] = d1 * inv * g[tid + 256] + b[tid + 256];
}

// ---------------- gating: softmax + top-2 ----------------
__global__ void k_gate(const float* __restrict__ x, const float* __restrict__ gW,
                       const float* __restrict__ gb)
{
    __shared__ float xs[D_];
    __shared__ float lg[E_];
    const int t = blockIdx.x;
    const int tid = threadIdx.x;     // 256
    xs[tid]       = x[(size_t)t * D_ + tid];
    xs[tid + 256] = x[(size_t)t * D_ + tid + 256];
    __syncthreads();

    const int e = tid >> 5;          // one warp per expert
    const int lane = tid & 31;
    float s = 0.f;
    for (int k = lane; k < D_; k += 32) s += xs[k] * gW[k * E_ + e];
    const unsigned m = 0xffffffffu;
#pragma unroll
    for (int o = 16; o > 0; o >>= 1) s += __shfl_down_sync(m, s, o);
    if (lane == 0) lg[e] = s + gb[e];
    __syncthreads();

    if (tid == 0) {
        float mx = lg[0];
#pragma unroll
        for (int k = 1; k < E_; k++) mx = fmaxf(mx, lg[k]);
        float ex[E_]; float sum = 0.f;
#pragma unroll
        for (int k = 0; k < E_; k++) { ex[k] = expf(lg[k] - mx); sum += ex[k]; }
        const float inv = 1.f / sum;
        int e0 = 0; float p0 = ex[0];
#pragma unroll
        for (int k = 1; k < E_; k++) if (ex[k] > p0) { p0 = ex[k]; e0 = k; }
        int e1 = -1; float p1 = -1.f;
#pragma unroll
        for (int k = 0; k < E_; k++)
            if (k != e0 && ex[k] > p1) { p1 = ex[k]; e1 = k; }
        g_te[2 * t]     = e0; g_tw[2 * t]     = p0 * inv;
        g_te[2 * t + 1] = e1; g_tw[2 * t + 1] = p1 * inv;
        atomicAdd(&g_cnt[e0], 1);
        atomicAdd(&g_cnt[e1], 1);
    }
}

__global__ void k_zero8() {
    if (threadIdx.x < E_) g_cnt[threadIdx.x] = 0;
}

__global__ void k_scan() {
    if (threadIdx.x == 0) {
        int a = 0;
        for (int e = 0; e < E_; e++) { g_off[e] = a; g_cur[e] = a; a += g_cnt[e]; }
        g_off[E_] = a;
    }
}

__global__ void k_scatter() {
    const int t = blockIdx.x * 256 + threadIdx.x;
    if (t >= NTOK) return;
#pragma unroll
    for (int k = 0; k < 2; k++) {
        const int e = g_te[2 * t + k];
        const int p = atomicAdd(&g_cur[e], 1);
        g_tok[p] = t;
        g_pos[2 * t + k] = p;
    }
}

// ---------------- LN2: out = LN(x + w0*eo[p0] + w1*eo[p1]) ----------------
__global__ void k_ln2(const float* __restrict__ x,
                      const float* __restrict__ g, const float* __restrict__ b,
                      float* __restrict__ out)
{
    __shared__ float red[8];
    const int t = blockIdx.x;
    const int tid = threadIdx.x;     // 256
    const int p0 = g_pos[2 * t], p1 = g_pos[2 * t + 1];
    const float w0 = g_tw[2 * t], w1 = g_tw[2 * t + 1];
    const float* e0 = g_eo + (size_t)p0 * D_;
    const float* e1 = g_eo + (size_t)p1 * D_;
    const float* xr = x + (size_t)t * D_;
    const float v0 = xr[tid]       + w0 * e0[tid]       + w1 * e1[tid];
    const float v1 = xr[tid + 256] + w0 * e0[tid + 256] + w1 * e1[tid + 256];
    const float mean = blk_sum_256(v0 + v1, red) * (1.f / D_);
    const float d0 = v0 - mean, d1 = v1 - mean;
    const float var = blk_sum_256(d0 * d0 + d1 * d1, red) * (1.f / D_);
    const float inv = rsqrtf(var + EPS_);
    out[(size_t)t * D_ + tid]       = d0 * inv * g[tid]       + b[tid];
    out[(size_t)t * D_ + tid + 256] = d1 * inv * g[tid + 256] + b[tid + 256];
}

// ---------------- host launcher ----------------
extern "C" void kernel_launch(void* const* d_in, const int* in_sizes, int n_in,
                              void* d_out, int out_size)
{
    const int*   src  = (const int*)  d_in[0];
    const float* frac = (const float*)d_in[1];
    const float* tab  = (const float*)d_in[2];
    const float* Wm2v = (const float*)d_in[3];
    const float* bm2v = (const float*)d_in[4];
    const float* pbW  = (const float*)d_in[5];
    const float* pbb  = (const float*)d_in[6];
    const float* pba  = (const float*)d_in[7];
    const float* Wk   = (const float*)d_in[8];
    const float* bk   = (const float*)d_in[9];
    const float* Wv   = (const float*)d_in[10];
    const float* bv   = (const float*)d_in[11];
    const float* Wo   = (const float*)d_in[12];
    const float* bo   = (const float*)d_in[13];
    const float* ln1g = (const float*)d_in[14];
    const float* ln1b = (const float*)d_in[15];
    const float* ln2g = (const float*)d_in[16];
    const float* ln2b = (const float*)d_in[17];
    const float* gW   = (const float*)d_in[18];
    const float* gb   = (const float*)d_in[19];
    const float* eW1  = (const float*)d_in[20];
    const float* eb1  = (const float*)d_in[21];
    const float* eW2  = (const float*)d_in[22];
    const float* eb2  = (const float*)d_in[23];

    float *x, *pb, *Kb, *Vb, *kvb, *wv, *o;
    cudaGetSymbolAddress((void**)&x,   g_x);
    cudaGetSymbolAddress((void**)&pb,  g_pb);
    cudaGetSymbolAddress((void**)&Kb,  g_K);
    cudaGetSymbolAddress((void**)&Vb,  g_V);
    cudaGetSymbolAddress((void**)&kvb, g_kv);
    cudaGetSymbolAddress((void**)&wv,  g_wv);
    cudaGetSymbolAddress((void**)&o,   g_o);

    const dim3 g44(4, 32);        // N=512 tiles x M=4096 tiles

    // x = embed_table[src] @ W_m2v + b
    k_embed<<<g44, 256>>>(src, tab, Wm2v, bm2v, x);
    // positional bias
    k_pb<<<(B_ * T_ * T_) / 256, 256>>>(frac, pbW, pbb, pba, pb);

    for (int i = 0; i < NL_; i++) {
        const size_t wOff = (size_t)i * D_ * D_;
        k_gemm<<<g44, 256>>>(x,  Wk + wOff, bk + i * D_, Kb, NTOK, D_, D_);
        k_gemm<<<g44, 256>>>(x,  Wv + wOff, bv + i * D_, Vb, NTOK, D_, D_);
        k_kv<<<B_, 512>>>(Kb, Vb, kvb);
        k_pbv<<<dim3(4, 1, B_), 256>>>(pb, Vb, kvb, wv);
        k_gemm<<<g44, 256>>>(wv, Wo + wOff, bo + i * D_, o, NTOK, D_, D_);
        k_ln<<<NTOK, 256>>>(x, o, ln1g + i * D_, ln1b + i * D_, x);

        k_zero8<<<1, 32>>>();
        k_gate<<<NTOK, 256>>>(x, gW + (size_t)i * D_ * E_, gb + i * E_);
        k_scan<<<1, 1>>>();
        k_scatter<<<NTOK / 256, 256>>>();

        k_moe1<<<dim3(FF_ / BN, 32, E_), 256>>>(
            x, eW1 + (size_t)i * E_ * D_ * FF_, eb1 + (size_t)i * E_ * FF_);
        k_moe2<<<dim3(D_ / BN, 32, E_), 256>>>(
            eW2 + (size_t)i * E_ * FF_ * D_, eb2 + (size_t)i * E_ * D_);

        float* dst = (i == NL_ - 1) ? (float*)d_out : x;
        k_ln2<<<NTOK, 256>>>(x, ln2g + i * D_, ln2b + i * D_, dst);
    }
}

// round 5
// speedup vs baseline: 1.9896x; 1.5417x over previous
#include <cuda_runtime.h>
#include <cuda_bf16.h>

// ---------------- problem constants ----------------
#define B_   32
#define T_   128
#define D_   512
#define H_   8
#define HD_  64
#define FF_  2048
#define E_   8
#define NL_  3
#define NF_  16
#define FEAT_ 200
#define NTOK  4096          // B*T
#define NSLOT 8192          // NTOK*2 (top-2 slots)
#define SCALE_ 10.0f
#define EPS_   1e-5f

// ---------------- scratch (device globals; no allocation allowed) ----------------
__device__ float g_x  [NTOK * D_];
__device__ float g_pb [B_ * T_ * T_];
__device__ float g_K  [NTOK * D_];
__device__ float g_V  [NTOK * D_];
__device__ float g_kv [B_ * D_];
__device__ float g_wv [NTOK * D_];
__device__ float g_o  [NTOK * D_];
__device__ float g_h  [(NSLOT + 128) * FF_];
__device__ float g_eo [(NSLOT + 128) * D_];
__device__ int   g_te [NSLOT];
__device__ float g_tw [NSLOT];
__device__ int   g_cnt[E_];
__device__ int   g_off[E_ + 1];
__device__ int   g_cur[E_];
__device__ int   g_tok[NSLOT + 128];
__device__ int   g_pos[NSLOT];

// ---------------- bf16x3 tensor-core GEMM core: 128x128x16 ----------------
#define BM 128
#define BN 128
#define BK 16
#define AW 12      // A smem row stride in words (8 + 4 pad -> conflict-free frags)
#define BW 136     // B smem row stride in words (128 + 8 pad)

__device__ __forceinline__ float4 ld4(const float* p) {
    return *reinterpret_cast<const float4*>(p);
}

// pack two floats as bf16x2 word: low half = lo, high half = hi
__device__ __forceinline__ unsigned pack2(float lo, float hi) {
    unsigned r;
    asm("cvt.rn.bf16x2.f32 %0, %1, %2;" : "=r"(r) : "f"(hi), "f"(lo));
    return r;
}

__device__ __forceinline__ void split_bf(float x, float& h, float& l) {
    h = __bfloat162float(__float2bfloat16_rn(x));
    l = x - h;
}

__device__ __forceinline__ void mma_bf16(float* c, const unsigned* a, const unsigned* b) {
    asm("mma.sync.aligned.m16n8k16.row.col.f32.bf16.bf16.f32 "
        "{%0,%1,%2,%3}, {%4,%5,%6,%7}, {%8,%9}, {%0,%1,%2,%3};"
        : "+f"(c[0]), "+f"(c[1]), "+f"(c[2]), "+f"(c[3])
        : "r"(a[0]), "r"(a[1]), "r"(a[2]), "r"(a[3]), "r"(b[0]), "r"(b[1]));
}

// C[M,N] = op( gather(A)[M,K] @ B[K,N] + bias + addvec )
// 256 threads = 8 warps (2x4), each warp 64x32 of m16n8k16 tiles, hi/lo split.
template <bool GATHER, bool RELU, bool ADDVEC>
__device__ __forceinline__ void gemm_tc(
    const float* __restrict__ A, int lda, const int* __restrict__ rowmap,
    const float* __restrict__ B, int ldb,
    const float* __restrict__ bias, const float* __restrict__ addvec,
    float* __restrict__ C, int ldc,
    int M, int N, int K, int mtile, int ntile)
{
    __shared__ unsigned Ash[2][BM][AW];   // bf16x2 words: word j = k pair (2j, 2j+1)
    __shared__ unsigned Asl[2][BM][AW];
    __shared__ unsigned Bsh[2][8][BW];    // [kp][n]: word = k pair (2kp, 2kp+1) at col n
    __shared__ unsigned Bsl[2][8][BW];

    const int tid  = threadIdx.x;
    const int lane = tid & 31;
    const int warp = tid >> 5;
    const int wm = (warp >> 2) * 64;      // 0 or 64
    const int wn = (warp & 3) * 32;       // 0,32,64,96
    const int gq  = lane >> 2;            // 0..7
    const int tig = lane & 3;             // 0..3

    // A tile loader: thread handles rows ar0, ar0+64; floats k = ac..ac+3 -> words wc, wc+1
    const int ar0 = tid >> 2;             // 0..63
    const int ac  = (tid & 3) * 4;
    const int wc  = (tid & 3) * 2;
    int gm0 = mtile * BM + ar0;       if (gm0 > M - 1) gm0 = M - 1;
    int gm1 = mtile * BM + ar0 + 64;  if (gm1 > M - 1) gm1 = M - 1;
    const int ra0 = GATHER ? rowmap[gm0] : gm0;
    const int ra1 = GATHER ? rowmap[gm1] : gm1;
    const float* Ap0 = A + (size_t)ra0 * lda + ac;
    const float* Ap1 = A + (size_t)ra1 * lda + ac;

    // B tile loader: thread handles k-rows 2*kp, 2*kp+1; cols bc..bc+3
    const int kp = tid >> 5;              // 0..7
    const int bc = (tid & 31) * 4;
    const float* Bp = B + (size_t)(2 * kp) * ldb + ntile * BN + bc;

    float acc[4][4][4];
#pragma unroll
    for (int i = 0; i < 4; i++)
#pragma unroll
        for (int j = 0; j < 4; j++)
#pragma unroll
            for (int r = 0; r < 4; r++) acc[i][j][r] = 0.f;

    const int nk = (K + BK - 1) / BK;
    const float4 z4 = make_float4(0.f, 0.f, 0.f, 0.f);

    float4 a0v, a1v, b0v, b1v;
    // prefetch tile 0 (K is a multiple of 8, so float4 guards are exact)
    a0v = (ac < K) ? ld4(Ap0) : z4;
    a1v = (ac < K) ? ld4(Ap1) : z4;
    b0v = (2 * kp < K) ? ld4(Bp) : z4;
    b1v = (2 * kp < K) ? ld4(Bp + ldb) : z4;

    for (int kt = 0; kt < nk; kt++) {
        const int s = kt & 1;
        // split + pack into smem
        {
            float h0, l0, h1, l1, h2, l2, h3, l3;
            split_bf(a0v.x, h0, l0); split_bf(a0v.y, h1, l1);
            split_bf(a0v.z, h2, l2); split_bf(a0v.w, h3, l3);
            *reinterpret_cast<uint2*>(&Ash[s][ar0][wc]) = make_uint2(pack2(h0, h1), pack2(h2, h3));
            *reinterpret_cast<uint2*>(&Asl[s][ar0][wc]) = make_uint2(pack2(l0, l1), pack2(l2, l3));
            split_bf(a1v.x, h0, l0); split_bf(a1v.y, h1, l1);
            split_bf(a1v.z, h2, l2); split_bf(a1v.w, h3, l3);
            *reinterpret_cast<uint2*>(&Ash[s][ar0 + 64][wc]) = make_uint2(pack2(h0, h1), pack2(h2, h3));
            *reinterpret_cast<uint2*>(&Asl[s][ar0 + 64][wc]) = make_uint2(pack2(l0, l1), pack2(l2, l3));
            float e0h, e0l, e1h, e1l, e2h, e2l, e3h, e3l;   // even-k (row 2kp)
            float o0h, o0l, o1h, o1l, o2h, o2l, o3h, o3l;   // odd-k  (row 2kp+1)
            split_bf(b0v.x, e0h, e0l); split_bf(b0v.y, e1h, e1l);
            split_bf(b0v.z, e2h, e2l); split_bf(b0v.w, e3h, e3l);
            split_bf(b1v.x, o0h, o0l); split_bf(b1v.y, o1h, o1l);
            split_bf(b1v.z, o2h, o2l); split_bf(b1v.w, o3h, o3l);
            *reinterpret_cast<uint4*>(&Bsh[s][kp][bc]) =
                make_uint4(pack2(e0h, o0h), pack2(e1h, o1h), pack2(e2h, o2h), pack2(e3h, o3h));
            *reinterpret_cast<uint4*>(&Bsl[s][kp][bc]) =
                make_uint4(pack2(e0l, o0l), pack2(e1l, o1l), pack2(e2l, o2l), pack2(e3l, o3l));
        }
        __syncthreads();

        if (kt + 1 < nk) {
            const int kb = (kt + 1) * BK;
            a0v = (kb + ac < K) ? ld4(Ap0 + kb) : z4;
            a1v = (kb + ac < K) ? ld4(Ap1 + kb) : z4;
            b0v = (kb + 2 * kp < K) ? ld4(Bp + (size_t)kb * ldb) : z4;
            b1v = (kb + 2 * kp < K) ? ld4(Bp + (size_t)(kb + 1) * ldb) : z4;
        }

        unsigned ahi[4][4], alo[4][4], bhi[4][2], blo[4][2];
#pragma unroll
        for (int mt = 0; mt < 4; mt++) {
            const int r0 = wm + mt * 16 + gq;
            ahi[mt][0] = Ash[s][r0]    [tig];
            ahi[mt][1] = Ash[s][r0 + 8][tig];
            ahi[mt][2] = Ash[s][r0]    [tig + 4];
            ahi[mt][3] = Ash[s][r0 + 8][tig + 4];
            alo[mt][0] = Asl[s][r0]    [tig];
            alo[mt][1] = Asl[s][r0 + 8][tig];
            alo[mt][2] = Asl[s][r0]    [tig + 4];
            alo[mt][3] = Asl[s][r0 + 8][tig + 4];
        }
#pragma unroll
        for (int nt = 0; nt < 4; nt++) {
            const int nn = wn + nt * 8 + gq;
            bhi[nt][0] = Bsh[s][tig]    [nn];
            bhi[nt][1] = Bsh[s][tig + 4][nn];
            blo[nt][0] = Bsl[s][tig]    [nn];
            blo[nt][1] = Bsl[s][tig + 4][nn];
        }
#pragma unroll
        for (int mt = 0; mt < 4; mt++)
#pragma unroll
            for (int nt = 0; nt < 4; nt++) {
                mma_bf16(acc[mt][nt], alo[mt], bhi[nt]);
                mma_bf16(acc[mt][nt], ahi[mt], blo[nt]);
                mma_bf16(acc[mt][nt], ahi[mt], bhi[nt]);
            }
        __syncthreads();
    }

    // epilogue: c0:(g, 2t) c1:(g, 2t+1) c2:(g+8, 2t) c3:(g+8, 2t+1)
#pragma unroll
    for (int nt = 0; nt < 4; nt++) {
        const int gn = ntile * BN + wn + nt * 8 + 2 * tig;
        float bx = 0.f, by = 0.f;
        if (bias) { bx = bias[gn]; by = bias[gn + 1]; }
        if (ADDVEC) { bx += addvec[gn]; by += addvec[gn + 1]; }
#pragma unroll
        for (int mt = 0; mt < 4; mt++) {
            const int gm0w = mtile * BM + wm + mt * 16 + gq;
            float v0 = acc[mt][nt][0] + bx;
            float v1 = acc[mt][nt][1] + by;
            float v2 = acc[mt][nt][2] + bx;
            float v3 = acc[mt][nt][3] + by;
            if (RELU) {
                v0 = fmaxf(v0, 0.f); v1 = fmaxf(v1, 0.f);
                v2 = fmaxf(v2, 0.f); v3 = fmaxf(v3, 0.f);
            }
            if (gm0w < M)
                *reinterpret_cast<float2*>(C + (size_t)gm0w * ldc + gn) = make_float2(v0, v1);
            if (gm0w + 8 < M)
                *reinterpret_cast<float2*>(C + (size_t)(gm0w + 8) * ldc + gn) = make_float2(v2, v3);
        }
    }
}

// ---------------- GEMM kernel wrappers ----------------
__global__ __launch_bounds__(256) void k_embed(
    const int* __restrict__ src, const float* __restrict__ tab,
    const float* __restrict__ W, const float* __restrict__ bias,
    float* __restrict__ C)
{
    gemm_tc<true, false, false>(tab, FEAT_, src, W, D_, bias, nullptr,
                                C, D_, NTOK, D_, FEAT_, blockIdx.y, blockIdx.x);
}

__global__ __launch_bounds__(256) void k_gemm(
    const float* __restrict__ A, const float* __restrict__ B,
    const float* __restrict__ bias, float* __restrict__ C,
    int M, int N, int K)
{
    gemm_tc<false, false, false>(A, K, nullptr, B, N, bias, nullptr,
                                 C, N, M, N, K, blockIdx.y, blockIdx.x);
}

__global__ __launch_bounds__(256) void k_pbv(
    const float* __restrict__ pb, const float* __restrict__ V,
    const float* __restrict__ kv, float* __restrict__ wv)
{
    const int b = blockIdx.z;
    gemm_tc<false, false, true>(pb + (size_t)b * T_ * T_, T_, nullptr,
                                V + (size_t)b * T_ * D_, D_,
                                nullptr, kv + (size_t)b * D_,
                                wv + (size_t)b * T_ * D_, D_,
                                T_, D_, T_, 0, blockIdx.x);
}

__global__ __launch_bounds__(256) void k_moe1(
    const float* __restrict__ x, const float* __restrict__ W1,
    const float* __restrict__ b1)
{
    const int e = blockIdx.z;
    const int Me = g_cnt[e];
    if ((int)(blockIdx.y * BM) >= Me) return;
    gemm_tc<true, true, false>(x, D_, g_tok + g_off[e],
                               W1 + (size_t)e * D_ * FF_, FF_,
                               b1 + (size_t)e * FF_, nullptr,
                               g_h + (size_t)g_off[e] * FF_, FF_,
                               Me, FF_, D_, blockIdx.y, blockIdx.x);
}

__global__ __launch_bounds__(256) void k_moe2(
    const float* __restrict__ W2, const float* __restrict__ b2)
{
    const int e = blockIdx.z;
    const int Me = g_cnt[e];
    if ((int)(blockIdx.y * BM) >= Me) return;
    gemm_tc<false, false, false>(g_h + (size_t)g_off[e] * FF_, FF_, nullptr,
                                 W2 + (size_t)e * FF_ * D_, D_,
                                 b2 + (size_t)e * D_, nullptr,
                                 g_eo + (size_t)g_off[e] * D_, D_,
                                 Me, D_, FF_, blockIdx.y, blockIdx.x);
}

// ---------------- Fourier positional bias ----------------
__global__ void k_pb(const float* __restrict__ frac,
                     const float* __restrict__ pbW,
                     const float* __restrict__ pbb,
                     const float* __restrict__ pba,
                     float* __restrict__ pb)
{
    __shared__ float w[NF_], ph[NF_], am[NF_];
    if (threadIdx.x < NF_) {
        w[threadIdx.x]  = pbW[threadIdx.x];
        ph[threadIdx.x] = pbb[threadIdx.x];
        am[threadIdx.x] = pba[threadIdx.x];
    }
    __syncthreads();
    const int idx = blockIdx.x * 256 + threadIdx.x;   // < 32*128*128
    const int j = idx & 127;
    const int i = (idx >> 7) & 127;
    const int b = idx >> 14;
    const float d = (frac[b * T_ + j] - frac[b * T_ + i]) * SCALE_;
    float s = 0.f;
#pragma unroll
    for (int f = 0; f < NF_; f++) s += am[f] * cosf(d * w[f] + ph[f]);
    pb[idx] = s;
}

// ---------------- kv reduction: kv[b,d] = sum_t K[b,t,d]*V[b,t,d] ----------------
__global__ void k_kv(const float* __restrict__ K, const float* __restrict__ V,
                     float* __restrict__ kv)
{
    const int b = blockIdx.x;
    const int d = threadIdx.x;     // 512 threads
    const float* Kb = K + (size_t)b * T_ * D_ + d;
    const float* Vb = V + (size_t)b * T_ * D_ + d;
    float s = 0.f;
#pragma unroll 8
    for (int t = 0; t < T_; t++) s += Kb[t * D_] * Vb[t * D_];
    kv[b * D_ + d] = s;
}

// ---------------- block reduction helper (256 threads) ----------------
__device__ __forceinline__ float blk_sum_256(float v, float* red) {
    const unsigned m = 0xffffffffu;
#pragma unroll
    for (int o = 16; o > 0; o >>= 1) v += __shfl_down_sync(m, v, o);
    if ((threadIdx.x & 31) == 0) red[threadIdx.x >> 5] = v;
    __syncthreads();
    if (threadIdx.x < 32) {
        float r = (threadIdx.x < 8) ? red[threadIdx.x] : 0.f;
#pragma unroll
        for (int o = 4; o > 0; o >>= 1) r += __shfl_down_sync(m, r, o);
        if (threadIdx.x == 0) red[0] = r;
    }
    __syncthreads();
    const float r = red[0];
    __syncthreads();
    return r;
}

// ---------------- LN1: out = LN(x + y) ----------------
__global__ void k_ln(const float* __restrict__ x, const float* __restrict__ y,
                     const float* __restrict__ g, const float* __restrict__ b,
                     float* __restrict__ out)
{
    __shared__ float red[8];
    const int t = blockIdx.x;
    const int tid = threadIdx.x;      // 256
    const float* xr = x + (size_t)t * D_;
    const float* yr = y + (size_t)t * D_;
    const float v0 = xr[tid]       + yr[tid];
    const float v1 = xr[tid + 256] + yr[tid + 256];
    const float mean = blk_sum_256(v0 + v1, red) * (1.f / D_);
    const float d0 = v0 - mean, d1 = v1 - mean;
    const float var = blk_sum_256(d0 * d0 + d1 * d1, red) * (1.f / D_);
    const float inv = rsqrtf(var + EPS_);
    out[(size_t)t * D_ + tid]       = d0 * inv * g[tid]       + b[tid];
    out[(size_t)t * D_ + tid + 256] = d1 * inv * g[tid + 256] + b[tid + 256];
}

// ---------------- gating: softmax + top-2 ----------------
__global__ void k_gate(const float* __restrict__ x, const float* __restrict__ gW,
                       const float* __restrict__ gb)
{
    __shared__ float xs[D_];
    __shared__ float lg[E_];
    const int t = blockIdx.x;
    const int tid = threadIdx.x;     // 256
    xs[tid]       = x[(size_t)t * D_ + tid];
    xs[tid + 256] = x[(size_t)t * D_ + tid + 256];
    __syncthreads();

    const int e = tid >> 5;          // one warp per expert
    const int lane = tid & 31;
    float s = 0.f;
    for (int k = lane; k < D_; k += 32) s += xs[k] * gW[k * E_ + e];
    const unsigned m = 0xffffffffu;
#pragma unroll
    for (int o = 16; o > 0; o >>= 1) s += __shfl_down_sync(m, s, o);
    if (lane == 0) lg[e] = s + gb[e];
    __syncthreads();

    if (tid == 0) {
        float mx = lg[0];
#pragma unroll
        for (int k = 1; k < E_; k++) mx = fmaxf(mx, lg[k]);
        float ex[E_]; float sum = 0.f;
#pragma unroll
        for (int k = 0; k < E_; k++) { ex[k] = expf(lg[k] - mx); sum += ex[k]; }
        const float inv = 1.f / sum;
        int e0 = 0; float p0 = ex[0];
#pragma unroll
        for (int k = 1; k < E_; k++) if (ex[k] > p0) { p0 = ex[k]; e0 = k; }
        int e1 = -1; float p1 = -1.f;
#pragma unroll
        for (int k = 0; k < E_; k++)
            if (k != e0 && ex[k] > p1) { p1 = ex[k]; e1 = k; }
        g_te[2 * t]     = e0; g_tw[2 * t]     = p0 * inv;
        g_te[2 * t + 1] = e1; g_tw[2 * t + 1] = p1 * inv;
        atomicAdd(&g_cnt[e0], 1);
        atomicAdd(&g_cnt[e1], 1);
    }
}

__global__ void k_zero8() {
    if (threadIdx.x < E_) g_cnt[threadIdx.x] = 0;
}

__global__ void k_scan() {
    if (threadIdx.x == 0) {
        int a = 0;
        for (int e = 0; e < E_; e++) { g_off[e] = a; g_cur[e] = a; a += g_cnt[e]; }
        g_off[E_] = a;
    }
}

__global__ void k_scatter() {
    const int t = blockIdx.x * 256 + threadIdx.x;
    if (t >= NTOK) return;
#pragma unroll
    for (int k = 0; k < 2; k++) {
        const int e = g_te[2 * t + k];
        const int p = atomicAdd(&g_cur[e], 1);
        g_tok[p] = t;
        g_pos[2 * t + k] = p;
    }
}

// ---------------- LN2: out = LN(x + w0*eo[p0] + w1*eo[p1]) ----------------
__global__ void k_ln2(const float* __restrict__ x,
                      const float* __restrict__ g, const float* __restrict__ b,
                      float* __restrict__ out)
{
    __shared__ float red[8];
    const int t = blockIdx.x;
    const int tid = threadIdx.x;     // 256
    const int p0 = g_pos[2 * t], p1 = g_pos[2 * t + 1];
    const float w0 = g_tw[2 * t], w1 = g_tw[2 * t + 1];
    const float* e0 = g_eo + (size_t)p0 * D_;
    const float* e1 = g_eo + (size_t)p1 * D_;
    const float* xr = x + (size_t)t * D_;
    const float v0 = xr[tid]       + w0 * e0[tid]       + w1 * e1[tid];
    const float v1 = xr[tid + 256] + w0 * e0[tid + 256] + w1 * e1[tid + 256];
    const float mean = blk_sum_256(v0 + v1, red) * (1.f / D_);
    const float d0 = v0 - mean, d1 = v1 - mean;
    const float var = blk_sum_256(d0 * d0 + d1 * d1, red) * (1.f / D_);
    const float inv = rsqrtf(var + EPS_);
    out[(size_t)t * D_ + tid]       = d0 * inv * g[tid]       + b[tid];
    out[(size_t)t * D_ + tid + 256] = d1 * inv * g[tid + 256] + b[tid + 256];
}

// ---------------- host launcher ----------------
extern "C" void kernel_launch(void* const* d_in, const int* in_sizes, int n_in,
                              void* d_out, int out_size)
{
    const int*   src  = (const int*)  d_in[0];
    const float* frac = (const float*)d_in[1];
    const float* tab  = (const float*)d_in[2];
    const float* Wm2v = (const float*)d_in[3];
    const float* bm2v = (const float*)d_in[4];
    const float* pbW  = (const float*)d_in[5];
    const float* pbb  = (const float*)d_in[6];
    const float* pba  = (const float*)d_in[7];
    const float* Wk   = (const float*)d_in[8];
    const float* bk   = (const float*)d_in[9];
    const float* Wv   = (const float*)d_in[10];
    const float* bv   = (const float*)d_in[11];
    const float* Wo   = (const float*)d_in[12];
    const float* bo   = (const float*)d_in[13];
    const float* ln1g = (const float*)d_in[14];
    const float* ln1b = (const float*)d_in[15];
    const float* ln2g = (const float*)d_in[16];
    const float* ln2b = (const float*)d_in[17];
    const float* gW   = (const float*)d_in[18];
    const float* gb   = (const float*)d_in[19];
    const float* eW1  = (const float*)d_in[20];
    const float* eb1  = (const float*)d_in[21];
    const float* eW2  = (const float*)d_in[22];
    const float* eb2  = (const float*)d_in[23];

    float *x, *pb, *Kb, *Vb, *kvb, *wv, *o;
    cudaGetSymbolAddress((void**)&x,   g_x);
    cudaGetSymbolAddress((void**)&pb,  g_pb);
    cudaGetSymbolAddress((void**)&Kb,  g_K);
    cudaGetSymbolAddress((void**)&Vb,  g_V);
    cudaGetSymbolAddress((void**)&kvb, g_kv);
    cudaGetSymbolAddress((void**)&wv,  g_wv);
    cudaGetSymbolAddress((void**)&o,   g_o);

    const dim3 g44(4, 32);        // N=512 tiles x M=4096 tiles

    // x = embed_table[src] @ W_m2v + b
    k_embed<<<g44, 256>>>(src, tab, Wm2v, bm2v, x);
    // positional bias
    k_pb<<<(B_ * T_ * T_) / 256, 256>>>(frac, pbW, pbb, pba, pb);

    for (int i = 0; i < NL_; i++) {
        const size_t wOff = (size_t)i * D_ * D_;
        k_gemm<<<g44, 256>>>(x,  Wk + wOff, bk + i * D_, Kb, NTOK, D_, D_);
        k_gemm<<<g44, 256>>>(x,  Wv + wOff, bv + i * D_, Vb, NTOK, D_, D_);
        k_kv<<<B_, 512>>>(Kb, Vb, kvb);
        k_pbv<<<dim3(4, 1, B_), 256>>>(pb, Vb, kvb, wv);
        k_gemm<<<g44, 256>>>(wv, Wo + wOff, bo + i * D_, o, NTOK, D_, D_);
        k_ln<<<NTOK, 256>>>(x, o, ln1g + i * D_, ln1b + i * D_, x);

        k_zero8<<<1, 32>>>();
        k_gate<<<NTOK, 256>>>(x, gW + (size_t)i * D_ * E_, gb + i * E_);
        k_scan<<<1, 1>>>();
        k_scatter<<<NTOK / 256, 256>>>();

        k_moe1<<<dim3(FF_ / BN, 32, E_), 256>>>(
            x, eW1 + (size_t)i * E_ * D_ * FF_, eb1 + (size_t)i * E_ * FF_);
        k_moe2<<<dim3(D_ / BN, 32, E_), 256>>>(
            eW2 + (size_t)i * E_ * FF_ * D_, eb2 + (size_t)i * E_ * D_);

        float* dst = (i == NL_ - 1) ? (float*)d_out : x;
        k_ln2<<<NTOK, 256>>>(x, ln2g + i * D_, ln2b + i * D_, dst);
    }
}